// round 1
// baseline (speedup 1.0000x reference)
#include <cuda_runtime.h>
#include <cuda_bf16.h>

// Gating_37598143709808
// x[B,256] -> h=relu(x@W1+b1)[B,256] -> logits=h@W2+b2 [B,5] -> top2 softmax scatter.
// Outputs: gates [B,5] f32, then top_idx [B,2] (written as float), concatenated in d_out.

#define Bdim 262144
#define Ddim 256
#define Hdim 256
#define Edim 5
#define TM   64      // rows per block
#define KC   32      // k-chunk

__global__ __launch_bounds__(256, 1)
void gating_fused_kernel(const float* __restrict__ x,
                         const float* __restrict__ W1,
                         const float* __restrict__ b1,
                         const float* __restrict__ W2,
                         const float* __restrict__ b2,
                         float* __restrict__ out_gates,
                         float* __restrict__ out_idx,
                         int write_idx)
{
    __shared__ float xs[TM][KC];      // 64*32*4 = 8 KB
    __shared__ float ws[KC][Hdim];    // 32*256*4 = 32 KB

    const int tid = threadIdx.x;
    const int ty  = tid >> 5;    // warp id 0..7  -> owns rows {ty, ty+8, ..., ty+56}
    const int tx  = tid & 31;    // lane          -> owns cols {tx, tx+32, ..., tx+224}
    const long long row0 = (long long)blockIdx.x * TM;

    float acc[8][8];
    #pragma unroll
    for (int i = 0; i < 8; i++)
        #pragma unroll
        for (int j = 0; j < 8; j++)
            acc[i][j] = 0.0f;

    // ---- GEMM1: h_tile[64][256] = x_tile @ W1 ----
    for (int kc = 0; kc < Ddim; kc += KC) {
        // load xs: 64x32 floats = 512 float4, 2 per thread
        {
            const float4* xg = reinterpret_cast<const float4*>(x);
            #pragma unroll
            for (int t = 0; t < 2; t++) {
                int v = tid + t * 256;          // 0..511
                int r  = v >> 3;                // row 0..63
                int c4 = v & 7;                 // float4 col 0..7
                float4 val = xg[((row0 + r) * Ddim + kc) / 4 + c4];
                xs[r][c4 * 4 + 0] = val.x;
                xs[r][c4 * 4 + 1] = val.y;
                xs[r][c4 * 4 + 2] = val.z;
                xs[r][c4 * 4 + 3] = val.w;
            }
        }
        // load ws: 32x256 floats = 2048 float4, 8 per thread
        {
            const float4* wg = reinterpret_cast<const float4*>(W1);
            #pragma unroll
            for (int t = 0; t < 8; t++) {
                int v  = tid + t * 256;         // 0..2047
                int r  = v >> 6;                // k row 0..31
                int c4 = v & 63;                // float4 col 0..63
                float4 val = wg[((kc + r) * Hdim) / 4 + c4];
                ws[r][c4 * 4 + 0] = val.x;
                ws[r][c4 * 4 + 1] = val.y;
                ws[r][c4 * 4 + 2] = val.z;
                ws[r][c4 * 4 + 3] = val.w;
            }
        }
        __syncthreads();

        #pragma unroll 4
        for (int k = 0; k < KC; k++) {
            float a[8], b[8];
            #pragma unroll
            for (int i = 0; i < 8; i++) a[i] = xs[ty + 8 * i][k];
            #pragma unroll
            for (int j = 0; j < 8; j++) b[j] = ws[k][tx + 32 * j];
            #pragma unroll
            for (int i = 0; i < 8; i++)
                #pragma unroll
                for (int j = 0; j < 8; j++)
                    acc[i][j] = fmaf(a[i], b[j], acc[i][j]);
        }
        __syncthreads();
    }

    // ---- fused epilogue: relu(+b1), contract with W2 -> partial logits ----
    float plog[8][Edim];
    #pragma unroll
    for (int i = 0; i < 8; i++)
        #pragma unroll
        for (int e = 0; e < Edim; e++)
            plog[i][e] = 0.0f;

    #pragma unroll
    for (int j = 0; j < 8; j++) {
        const int n = tx + 32 * j;
        const float bb1 = __ldg(&b1[n]);
        float w2e[Edim];
        #pragma unroll
        for (int e = 0; e < Edim; e++) w2e[e] = __ldg(&W2[n * Edim + e]);
        #pragma unroll
        for (int i = 0; i < 8; i++) {
            float h = acc[i][j] + bb1;
            h = fmaxf(h, 0.0f);
            #pragma unroll
            for (int e = 0; e < Edim; e++)
                plog[i][e] = fmaf(h, w2e[e], plog[i][e]);
        }
    }

    // warp-reduce partial logits (lanes hold disjoint n-slices of the same rows)
    #pragma unroll
    for (int off = 16; off > 0; off >>= 1) {
        #pragma unroll
        for (int i = 0; i < 8; i++)
            #pragma unroll
            for (int e = 0; e < Edim; e++)
                plog[i][e] += __shfl_xor_sync(0xffffffffu, plog[i][e], off);
    }

    // ---- lane 0: top-2, softmax over the two, scatter ----
    if (tx == 0) {
        float bb2[Edim];
        #pragma unroll
        for (int e = 0; e < Edim; e++) bb2[e] = __ldg(&b2[e]);

        #pragma unroll
        for (int i = 0; i < 8; i++) {
            const long long row = row0 + ty + 8 * i;
            float l[Edim];
            #pragma unroll
            for (int e = 0; e < Edim; e++) l[e] = plog[i][e] + bb2[e];

            // argmax (first occurrence on ties, matching top_k stability)
            int i1 = 0;
            #pragma unroll
            for (int e = 1; e < Edim; e++) if (l[e] > l[i1]) i1 = e;
            int i2 = (i1 == 0) ? 1 : 0;
            #pragma unroll
            for (int e = 0; e < Edim; e++)
                if (e != i1 && l[e] > l[i2]) i2 = e;

            // softmax over {l[i1], l[i2]} (l[i1] is the max)
            float e2 = __expf(l[i2] - l[i1]);
            float inv = 1.0f / (1.0f + e2);
            float g1 = inv;
            float g2 = e2 * inv;

            #pragma unroll
            for (int e = 0; e < Edim; e++) {
                float g = (e == i1) ? g1 : ((e == i2) ? g2 : 0.0f);
                out_gates[row * Edim + e] = g;
            }
            if (write_idx) {
                out_idx[row * 2 + 0] = (float)i1;
                out_idx[row * 2 + 1] = (float)i2;
            }
        }
    }
}

extern "C" void kernel_launch(void* const* d_in, const int* in_sizes, int n_in,
                              void* d_out, int out_size)
{
    const float* x  = (const float*)d_in[0];
    const float* W1 = (const float*)d_in[1];
    const float* b1 = (const float*)d_in[2];
    const float* W2 = (const float*)d_in[3];
    const float* b2 = (const float*)d_in[4];

    const long long Brows = (long long)in_sizes[0] / Ddim;   // 262144

    float* gates = (float*)d_out;
    float* idxf  = gates + Brows * Edim;
    int write_idx = ((long long)out_size >= Brows * (Edim + 2)) ? 1 : 0;

    dim3 grid((unsigned)(Brows / TM));
    dim3 block(256);
    gating_fused_kernel<<<grid, block>>>(x, W1, b1, W2, b2, gates, idxf, write_idx);
}

// round 3
// speedup vs baseline: 1.9136x; 1.9136x over previous
#include <cuda_runtime.h>
#include <cuda_bf16.h>
#include <cstdint>

// ===================== problem constants =====================
#define DDIM 256
#define HDIM 256
#define EDIM 5
#define BM   64          // rows per CTA
#define KC   32          // k per smem chunk (2 mma k-steps)
#define NCHUNK (DDIM / KC)
#define TAU  4e-3f
#define FIXCAP 8192

// padded smem leading dims (bf16 elements)
#define XS_LD 40         // 64 rows,  stride 80B  -> ldmatrix phase conflict-free
#define WS_LD 264        // 32 rows,  stride 528B -> ldmatrix phase conflict-free

// dynamic smem byte offsets
#define XS_HI_OFF 0
#define XS_LO_OFF 5120
#define WS_HI_OFF 10240
#define WS_LO_OFF 27136
#define PLOG_OFF  44032   // float[64][4][5]
#define B1_OFF    49152   // float[256]
#define W2_OFF    50176   // float[256*5]
#define B2_OFF    55296   // float[8]
#define SMEM_TOTAL 55424

// ===================== device scratch =====================
__device__ int g_count;
__device__ int g_rows[FIXCAP];

// ===================== PTX helpers =====================
__device__ __forceinline__ uint32_t smem_u32(const void* p) {
    uint32_t a;
    asm("{ .reg .u64 t; cvta.to.shared.u64 t, %1; cvt.u32.u64 %0, t; }" : "=r"(a) : "l"(p));
    return a;
}

#define LDSM_X4(r0, r1, r2, r3, addr)                                              \
    asm volatile("ldmatrix.sync.aligned.m8n8.x4.shared.b16 {%0,%1,%2,%3}, [%4];"   \
        : "=r"(r0), "=r"(r1), "=r"(r2), "=r"(r3) : "r"(addr))

#define LDSM_X4_T(r0, r1, r2, r3, addr)                                            \
    asm volatile("ldmatrix.sync.aligned.m8n8.x4.trans.shared.b16 {%0,%1,%2,%3}, [%4];" \
        : "=r"(r0), "=r"(r1), "=r"(r2), "=r"(r3) : "r"(addr))

#define MMA_BF16(d, a, b0, b1)                                                     \
    asm volatile("mma.sync.aligned.m16n8k16.row.col.f32.bf16.bf16.f32 "            \
        "{%0,%1,%2,%3}, {%4,%5,%6,%7}, {%8,%9}, {%0,%1,%2,%3};"                    \
        : "+f"((d)[0]), "+f"((d)[1]), "+f"((d)[2]), "+f"((d)[3])                   \
        : "r"((a)[0]), "r"((a)[1]), "r"((a)[2]), "r"((a)[3]), "r"(b0), "r"(b1))

__device__ __forceinline__ uint32_t pack_bf16x2(float a, float b) {
    __nv_bfloat162 v = __floats2bfloat162_rn(a, b);
    return *reinterpret_cast<uint32_t*>(&v);
}

// ===================== kernel 0: zero flag counter =====================
__global__ void zero_kernel() { g_count = 0; }

// ===================== kernel 1: main fused mma kernel =====================
__global__ __launch_bounds__(256, 1)
void gating_mma_kernel(const float* __restrict__ x,
                       const float* __restrict__ W1,
                       const float* __restrict__ b1,
                       const float* __restrict__ W2,
                       const float* __restrict__ b2,
                       float* __restrict__ out_gates,
                       float* __restrict__ out_idx,
                       int write_idx)
{
    extern __shared__ __align__(128) char smem[];
    const uint32_t sb = smem_u32(smem);
    const int tid  = threadIdx.x;
    const int wrp  = tid >> 5;
    const int ln   = tid & 31;
    const int mw   = wrp >> 2;           // 0..1 : warp row-block (32 rows)
    const int nw   = wrp & 3;            // 0..3 : warp col-block (64 cols)
    const long long row0 = (long long)blockIdx.x * BM;

    __nv_bfloat16* xs_hi = (__nv_bfloat16*)(smem + XS_HI_OFF);
    __nv_bfloat16* xs_lo = (__nv_bfloat16*)(smem + XS_LO_OFF);
    __nv_bfloat16* ws_hi = (__nv_bfloat16*)(smem + WS_HI_OFF);
    __nv_bfloat16* ws_lo = (__nv_bfloat16*)(smem + WS_LO_OFF);
    float* plog = (float*)(smem + PLOG_OFF);
    float* b1s  = (float*)(smem + B1_OFF);
    float* w2s  = (float*)(smem + W2_OFF);
    float* b2s  = (float*)(smem + B2_OFF);

    // aux tables
    b1s[tid] = b1[tid];
    if (tid < EDIM) b2s[tid] = b2[tid];
    #pragma unroll
    for (int i = 0; i < 5; i++) {
        int v = tid + i * 256;
        if (v < HDIM * EDIM) w2s[v] = W2[v];
    }

    float c[2][8][4];
    #pragma unroll
    for (int mt = 0; mt < 2; mt++)
        #pragma unroll
        for (int nt = 0; nt < 8; nt++)
            #pragma unroll
            for (int r = 0; r < 4; r++)
                c[mt][nt][r] = 0.0f;

    for (int kc = 0; kc < NCHUNK; kc++) {
        // ---- load + split x tile: 64 x 32 f32 ----
        {
            const float4* xg = (const float4*)x;
            #pragma unroll
            for (int t = 0; t < 2; t++) {
                int v  = tid + t * 256;           // 0..511
                int r  = v >> 3;                  // row 0..63
                int c4 = v & 7;                   // float4 col
                float4 val = xg[((row0 + r) * DDIM + kc * KC) / 4 + c4];
                float hx = __bfloat162float(__float2bfloat16_rn(val.x));
                float hy = __bfloat162float(__float2bfloat16_rn(val.y));
                float hz = __bfloat162float(__float2bfloat16_rn(val.z));
                float hw = __bfloat162float(__float2bfloat16_rn(val.w));
                uint32_t* ph = (uint32_t*)(xs_hi + r * XS_LD + c4 * 4);
                uint32_t* pl = (uint32_t*)(xs_lo + r * XS_LD + c4 * 4);
                ph[0] = pack_bf16x2(hx, hy);
                ph[1] = pack_bf16x2(hz, hw);
                pl[0] = pack_bf16x2(val.x - hx, val.y - hy);
                pl[1] = pack_bf16x2(val.z - hz, val.w - hw);
            }
        }
        // ---- load + split W1 tile: 32 x 256 f32 (row-major [k][n]) ----
        {
            const float4* wg = (const float4*)W1;
            #pragma unroll
            for (int t = 0; t < 8; t++) {
                int v  = tid + t * 256;           // 0..2047
                int k  = v >> 6;                  // 0..31
                int c4 = v & 63;
                float4 val = wg[((long long)(kc * KC + k) * HDIM) / 4 + c4];
                float hx = __bfloat162float(__float2bfloat16_rn(val.x));
                float hy = __bfloat162float(__float2bfloat16_rn(val.y));
                float hz = __bfloat162float(__float2bfloat16_rn(val.z));
                float hw = __bfloat162float(__float2bfloat16_rn(val.w));
                uint32_t* ph = (uint32_t*)(ws_hi + k * WS_LD + c4 * 4);
                uint32_t* pl = (uint32_t*)(ws_lo + k * WS_LD + c4 * 4);
                ph[0] = pack_bf16x2(hx, hy);
                ph[1] = pack_bf16x2(hz, hw);
                pl[0] = pack_bf16x2(val.x - hx, val.y - hy);
                pl[1] = pack_bf16x2(val.z - hz, val.w - hw);
            }
        }
        __syncthreads();

        #pragma unroll
        for (int ks = 0; ks < 2; ks++) {
            const int k0 = ks * 16;
            uint32_t a_hi[2][4], a_lo[2][4];
            {
                int ar = mw * 32 + (ln & 15);
                int ac = k0 + (ln >> 4) * 8;
                uint32_t off = (uint32_t)((ar * XS_LD + ac) * 2);
                LDSM_X4(a_hi[0][0], a_hi[0][1], a_hi[0][2], a_hi[0][3], sb + XS_HI_OFF + off);
                LDSM_X4(a_lo[0][0], a_lo[0][1], a_lo[0][2], a_lo[0][3], sb + XS_LO_OFF + off);
                uint32_t off2 = off + (uint32_t)(16 * XS_LD * 2);
                LDSM_X4(a_hi[1][0], a_hi[1][1], a_hi[1][2], a_hi[1][3], sb + XS_HI_OFF + off2);
                LDSM_X4(a_lo[1][0], a_lo[1][1], a_lo[1][2], a_lo[1][3], sb + XS_LO_OFF + off2);
            }
            uint32_t b_hi[4][4], b_lo[4][4];
            {
                int br = k0 + (ln & 7) + ((ln >> 3) & 1) * 8;
                #pragma unroll
                for (int ng = 0; ng < 4; ng++) {
                    int bc = nw * 64 + ng * 16 + (ln >> 4) * 8;
                    uint32_t off = (uint32_t)((br * WS_LD + bc) * 2);
                    LDSM_X4_T(b_hi[ng][0], b_hi[ng][1], b_hi[ng][2], b_hi[ng][3], sb + WS_HI_OFF + off);
                    LDSM_X4_T(b_lo[ng][0], b_lo[ng][1], b_lo[ng][2], b_lo[ng][3], sb + WS_LO_OFF + off);
                }
            }
            #pragma unroll
            for (int mt = 0; mt < 2; mt++)
                #pragma unroll
                for (int ng = 0; ng < 4; ng++)
                    #pragma unroll
                    for (int hf = 0; hf < 2; hf++) {
                        const int nt = ng * 2 + hf;
                        MMA_BF16(c[mt][nt], a_hi[mt], b_hi[ng][hf * 2], b_hi[ng][hf * 2 + 1]);
                        MMA_BF16(c[mt][nt], a_hi[mt], b_lo[ng][hf * 2], b_lo[ng][hf * 2 + 1]);
                        MMA_BF16(c[mt][nt], a_lo[mt], b_hi[ng][hf * 2], b_hi[ng][hf * 2 + 1]);
                    }
        }
        __syncthreads();
    }

    // ---- fused epilogue ----
    float pl[2][2][EDIM];
    #pragma unroll
    for (int mt = 0; mt < 2; mt++)
        #pragma unroll
        for (int h = 0; h < 2; h++)
            #pragma unroll
            for (int e = 0; e < EDIM; e++)
                pl[mt][h][e] = 0.0f;

    #pragma unroll
    for (int nt = 0; nt < 8; nt++)
        #pragma unroll
        for (int i = 0; i < 2; i++) {
            const int cc = nw * 64 + nt * 8 + (ln & 3) * 2 + i;
            const float bb = b1s[cc];
            float w2e[EDIM];
            #pragma unroll
            for (int e = 0; e < EDIM; e++) w2e[e] = w2s[cc * EDIM + e];
            #pragma unroll
            for (int mt = 0; mt < 2; mt++)
                #pragma unroll
                for (int h = 0; h < 2; h++) {
                    float hv = fmaxf(c[mt][nt][h * 2 + i] + bb, 0.0f);
                    #pragma unroll
                    for (int e = 0; e < EDIM; e++)
                        pl[mt][h][e] = fmaf(hv, w2e[e], pl[mt][h][e]);
                }
        }

    #pragma unroll
    for (int off = 1; off < 4; off <<= 1)
        #pragma unroll
        for (int mt = 0; mt < 2; mt++)
            #pragma unroll
            for (int h = 0; h < 2; h++)
                #pragma unroll
                for (int e = 0; e < EDIM; e++)
                    pl[mt][h][e] += __shfl_xor_sync(0xffffffffu, pl[mt][h][e], off);

    if ((ln & 3) == 0) {
        #pragma unroll
        for (int mt = 0; mt < 2; mt++)
            #pragma unroll
            for (int h = 0; h < 2; h++) {
                const int r = mw * 32 + mt * 16 + (ln >> 2) + 8 * h;
                #pragma unroll
                for (int e = 0; e < EDIM; e++)
                    plog[(r * 4 + nw) * EDIM + e] = pl[mt][h][e];
            }
    }
    __syncthreads();

    if (tid < BM) {
        const long long row = row0 + tid;
        float l[EDIM];
        #pragma unroll
        for (int e = 0; e < EDIM; e++) {
            float s = b2s[e];
            #pragma unroll
            for (int w = 0; w < 4; w++) s += plog[(tid * 4 + w) * EDIM + e];
            l[e] = s;
        }
        int i1 = 0;
        #pragma unroll
        for (int e = 1; e < EDIM; e++) if (l[e] > l[i1]) i1 = e;
        int i2 = (i1 == 0) ? 1 : 0;
        #pragma unroll
        for (int e = 0; e < EDIM; e++) if (e != i1 && l[e] > l[i2]) i2 = e;
        float m3 = -3.4e38f;
        #pragma unroll
        for (int e = 0; e < EDIM; e++) if (e != i1 && e != i2 && l[e] > m3) m3 = l[e];

        float e2  = __expf(l[i2] - l[i1]);
        float inv = 1.0f / (1.0f + e2);
        #pragma unroll
        for (int e = 0; e < EDIM; e++)
            out_gates[row * EDIM + e] = (e == i1) ? inv : ((e == i2) ? e2 * inv : 0.0f);
        if (write_idx) {
            out_idx[row * 2 + 0] = (float)i1;
            out_idx[row * 2 + 1] = (float)i2;
        }
        if ((l[i1] - l[i2] < TAU) || (l[i2] - m3 < TAU)) {
            int pos = atomicAdd(&g_count, 1);
            if (pos < FIXCAP) g_rows[pos] = (int)row;
        }
    }
}

// ===================== kernel 2: exact fp32 fixup =====================
__global__ __launch_bounds__(256)
void fixup_kernel(const float* __restrict__ x,
                  const float* __restrict__ W1,
                  const float* __restrict__ b1,
                  const float* __restrict__ W2,
                  const float* __restrict__ b2,
                  float* __restrict__ out_gates,
                  float* __restrict__ out_idx,
                  int write_idx)
{
    int cnt = g_count; if (cnt > FIXCAP) cnt = FIXCAP;
    if ((int)blockIdx.x >= cnt) return;
    const int row = g_rows[blockIdx.x];
    const int tid = threadIdx.x;

    __shared__ float xs[DDIM];
    __shared__ float red[8][EDIM];
    xs[tid] = x[(long long)row * DDIM + tid];
    __syncthreads();

    float dot = 0.f;
    #pragma unroll 8
    for (int k = 0; k < DDIM; k++)
        dot = fmaf(xs[k], W1[k * HDIM + tid], dot);
    float h = fmaxf(dot + b1[tid], 0.f);

    float pl[EDIM];
    #pragma unroll
    for (int e = 0; e < EDIM; e++) pl[e] = h * W2[tid * EDIM + e];
    #pragma unroll
    for (int off = 16; off > 0; off >>= 1)
        #pragma unroll
        for (int e = 0; e < EDIM; e++)
            pl[e] += __shfl_xor_sync(0xffffffffu, pl[e], off);
    if ((tid & 31) == 0)
        #pragma unroll
        for (int e = 0; e < EDIM; e++) red[tid >> 5][e] = pl[e];
    __syncthreads();

    if (tid == 0) {
        float l[EDIM];
        #pragma unroll
        for (int e = 0; e < EDIM; e++) {
            float s = b2[e];
            #pragma unroll
            for (int w = 0; w < 8; w++) s += red[w][e];
            l[e] = s;
        }
        int i1 = 0;
        #pragma unroll
        for (int e = 1; e < EDIM; e++) if (l[e] > l[i1]) i1 = e;
        int i2 = (i1 == 0) ? 1 : 0;
        #pragma unroll
        for (int e = 0; e < EDIM; e++) if (e != i1 && l[e] > l[i2]) i2 = e;
        float e2  = __expf(l[i2] - l[i1]);
        float inv = 1.0f / (1.0f + e2);
        #pragma unroll
        for (int e = 0; e < EDIM; e++)
            out_gates[(long long)row * EDIM + e] = (e == i1) ? inv : ((e == i2) ? e2 * inv : 0.0f);
        if (write_idx) {
            out_idx[(long long)row * 2 + 0] = (float)i1;
            out_idx[(long long)row * 2 + 1] = (float)i2;
        }
    }
}

// ===================== launcher =====================
extern "C" void kernel_launch(void* const* d_in, const int* in_sizes, int n_in,
                              void* d_out, int out_size)
{
    const float* x  = (const float*)d_in[0];
    const float* W1 = (const float*)d_in[1];
    const float* b1 = (const float*)d_in[2];
    const float* W2 = (const float*)d_in[3];
    const float* b2 = (const float*)d_in[4];

    const long long Brows = (long long)in_sizes[0] / DDIM;
    float* gates = (float*)d_out;
    float* idxf  = gates + Brows * EDIM;
    int write_idx = ((long long)out_size >= Brows * (EDIM + 2)) ? 1 : 0;

    cudaFuncSetAttribute(gating_mma_kernel,
                         cudaFuncAttributeMaxDynamicSharedMemorySize, SMEM_TOTAL);

    zero_kernel<<<1, 1>>>();
    gating_mma_kernel<<<(unsigned)(Brows / BM), 256, SMEM_TOTAL>>>(
        x, W1, b1, W2, b2, gates, idxf, write_idx);
    fixup_kernel<<<FIXCAP, 256>>>(x, W1, b1, W2, b2, gates, idxf, write_idx);
}

// round 4
// speedup vs baseline: 3.9844x; 2.0821x over previous
#include <cuda_runtime.h>
#include <cuda_fp16.h>
#include <cstdint>

// ===================== problem constants =====================
#define DDIM 256
#define HDIM 256
#define EDIM 5
#define BM   64            // rows per CTA
#define KC   32            // k per smem chunk (2 mma k-steps)
#define NCHUNK (DDIM / KC)
#define TAU  3e-3f
#define FIXCAP 16384
#define RPF  16            // rows per fixup block

// padded smem leading dims (fp16 elements)
#define XS_LD 40           // 64 rows, stride 80B
#define WS_LD 264          // 32 rows, stride 528B (16B-aligned)

// dynamic smem byte offsets
#define XS0_OFF   0        // 64*40*2 = 5120
#define XS1_OFF   5120
#define WS0_OFF   10240    // 32*264*2 = 16896
#define WS1_OFF   27136
#define PLOG_OFF  44032    // float[64][4][5] = 5120
#define B1_OFF    49152    // float[256]
#define W2_OFF    50176    // float[256*5]
#define B2_OFF    55296    // float[8]
#define SMEM_TOTAL 55424

// ===================== device scratch =====================
__device__ int    g_count;
__device__ int    g_rows[FIXCAP];
__device__ __half g_w1h[DDIM * HDIM];   // W1 pre-converted to fp16, row-major [k][n]

// ===================== PTX helpers =====================
__device__ __forceinline__ uint32_t smem_u32(const void* p) {
    uint32_t a;
    asm("{ .reg .u64 t; cvta.to.shared.u64 t, %1; cvt.u32.u64 %0, t; }" : "=r"(a) : "l"(p));
    return a;
}

#define LDSM_X4(r0, r1, r2, r3, addr)                                              \
    asm volatile("ldmatrix.sync.aligned.m8n8.x4.shared.b16 {%0,%1,%2,%3}, [%4];"   \
        : "=r"(r0), "=r"(r1), "=r"(r2), "=r"(r3) : "r"(addr))

#define LDSM_X4_T(r0, r1, r2, r3, addr)                                            \
    asm volatile("ldmatrix.sync.aligned.m8n8.x4.trans.shared.b16 {%0,%1,%2,%3}, [%4];" \
        : "=r"(r0), "=r"(r1), "=r"(r2), "=r"(r3) : "r"(addr))

#define MMA_F16(d, a, b0, b1)                                                      \
    asm volatile("mma.sync.aligned.m16n8k16.row.col.f32.f16.f16.f32 "              \
        "{%0,%1,%2,%3}, {%4,%5,%6,%7}, {%8,%9}, {%0,%1,%2,%3};"                    \
        : "+f"((d)[0]), "+f"((d)[1]), "+f"((d)[2]), "+f"((d)[3])                   \
        : "r"((a)[0]), "r"((a)[1]), "r"((a)[2]), "r"((a)[3]), "r"(b0), "r"(b1))

#define CP_ASYNC16(dst, src)                                                       \
    asm volatile("cp.async.cg.shared.global [%0], [%1], 16;" :: "r"(dst), "l"(src))
#define CP_COMMIT() asm volatile("cp.async.commit_group;" ::: "memory")
#define CP_WAIT0()  asm volatile("cp.async.wait_group 0;" ::: "memory")

__device__ __forceinline__ uint32_t pack_h2(float a, float b) {
    __half2 v = __floats2half2_rn(a, b);
    return *reinterpret_cast<uint32_t*>(&v);
}

// ===================== kernel 0: prep (W1 -> fp16, zero counter) =====================
__global__ __launch_bounds__(256)
void prep_kernel(const float* __restrict__ W1) {
    int i = blockIdx.x * 256 + threadIdx.x;
    g_w1h[i] = __float2half(W1[i]);
    if (i == 0) g_count = 0;
}

// ===================== kernel 1: main fused mma kernel =====================
__global__ __launch_bounds__(256, 1)
void gating_mma_kernel(const float* __restrict__ x,
                       const float* __restrict__ b1,
                       const float* __restrict__ W2,
                       const float* __restrict__ b2,
                       float* __restrict__ out_gates,
                       float* __restrict__ out_idx,
                       int write_idx)
{
    extern __shared__ __align__(128) char smem[];
    const uint32_t sb = smem_u32(smem);
    const int tid  = threadIdx.x;
    const int wrp  = tid >> 5;
    const int ln   = tid & 31;
    const int mw   = wrp >> 2;           // 0..1 : warp row-block (32 rows)
    const int nw   = wrp & 3;            // 0..3 : warp col-block (64 cols)
    const long long row0 = (long long)blockIdx.x * BM;

    float* plog = (float*)(smem + PLOG_OFF);
    float* b1s  = (float*)(smem + B1_OFF);
    float* w2s  = (float*)(smem + W2_OFF);
    float* b2s  = (float*)(smem + B2_OFF);

    // aux tables
    b1s[tid] = b1[tid];
    if (tid < EDIM) b2s[tid] = b2[tid];
    #pragma unroll
    for (int i = 0; i < 5; i++) {
        int v = tid + i * 256;
        if (v < HDIM * EDIM) w2s[v] = W2[v];
    }

    // per-thread load indices
    const int xr0 = tid >> 3;            // x row for t=0 (0..31)
    const int xc4 = tid & 7;             // float4 col
    const int wrow = tid >> 3;           // W row for t=0 (0..31)
    const int wgrp = tid & 7;            // 16B group base (of 32 per row)

    auto cp_async_W = [&](int chunk, uint32_t ws_off) {
        const __half* src_base = g_w1h + (size_t)(chunk * KC) * HDIM;
        #pragma unroll
        for (int t = 0; t < 4; t++) {
            int v   = tid + t * 256;     // 0..1023
            int r   = v >> 5;            // 0..31
            int g   = v & 31;            // 0..31
            uint32_t dst = sb + ws_off + (uint32_t)(r * (WS_LD * 2) + g * 16);
            CP_ASYNC16(dst, src_base + r * HDIM + g * 8);
        }
    };
    auto load_x_regs = [&](int chunk, float4* xv) {
        const float4* xg = (const float4*)x;
        #pragma unroll
        for (int t = 0; t < 2; t++) {
            int r = xr0 + t * 32;        // 0..63
            xv[t] = xg[((row0 + r) * DDIM + chunk * KC) / 4 + xc4];
        }
    };
    auto store_x = [&](const float4* xv, uint32_t xs_off) {
        #pragma unroll
        for (int t = 0; t < 2; t++) {
            int r = xr0 + t * 32;
            uint32_t* p = (uint32_t*)(smem + xs_off + (r * XS_LD + xc4 * 4) * 2);
            p[0] = pack_h2(xv[t].x, xv[t].y);
            p[1] = pack_h2(xv[t].z, xv[t].w);
        }
    };

    float c[2][8][4];
    #pragma unroll
    for (int mt = 0; mt < 2; mt++)
        #pragma unroll
        for (int nt = 0; nt < 8; nt++)
            #pragma unroll
            for (int r = 0; r < 4; r++)
                c[mt][nt][r] = 0.0f;

    // prologue
    float4 xv[2], xv2[2];
    load_x_regs(0, xv);
    cp_async_W(0, WS0_OFF);
    CP_COMMIT();

    #pragma unroll
    for (int kc = 0; kc < NCHUNK; kc++) {
        const int b = kc & 1;
        const uint32_t xs_off = b ? XS1_OFF : XS0_OFF;
        const uint32_t ws_off = b ? WS1_OFF : WS0_OFF;

        CP_WAIT0();                      // W chunk kc resident
        store_x(xv, xs_off);
        if (kc + 1 < NCHUNK) load_x_regs(kc + 1, xv2);
        __syncthreads();
        if (kc + 1 < NCHUNK) {
            cp_async_W(kc + 1, b ? WS0_OFF : WS1_OFF);
            CP_COMMIT();
        }

        #pragma unroll
        for (int ks = 0; ks < 2; ks++) {
            const int k0 = ks * 16;
            uint32_t a[2][4];
            {
                int ar = mw * 32 + (ln & 15);
                int ac = k0 + (ln >> 4) * 8;
                uint32_t off = (uint32_t)((ar * XS_LD + ac) * 2);
                LDSM_X4(a[0][0], a[0][1], a[0][2], a[0][3], sb + xs_off + off);
                uint32_t off2 = off + (uint32_t)(16 * XS_LD * 2);
                LDSM_X4(a[1][0], a[1][1], a[1][2], a[1][3], sb + xs_off + off2);
            }
            uint32_t bfr[4][4];
            {
                int br = k0 + (ln & 7) + ((ln >> 3) & 1) * 8;
                #pragma unroll
                for (int ng = 0; ng < 4; ng++) {
                    int bc = nw * 64 + ng * 16 + (ln >> 4) * 8;
                    uint32_t off = (uint32_t)((br * WS_LD + bc) * 2);
                    LDSM_X4_T(bfr[ng][0], bfr[ng][1], bfr[ng][2], bfr[ng][3], sb + ws_off + off);
                }
            }
            #pragma unroll
            for (int mt = 0; mt < 2; mt++)
                #pragma unroll
                for (int ng = 0; ng < 4; ng++)
                    #pragma unroll
                    for (int hf = 0; hf < 2; hf++)
                        MMA_F16(c[mt][ng * 2 + hf], a[mt], bfr[ng][hf * 2], bfr[ng][hf * 2 + 1]);
        }
        xv[0] = xv2[0]; xv[1] = xv2[1];
    }

    // ---- fused epilogue: bias + relu + GEMM2 partials ----
    float pl[2][2][EDIM];
    #pragma unroll
    for (int mt = 0; mt < 2; mt++)
        #pragma unroll
        for (int h = 0; h < 2; h++)
            #pragma unroll
            for (int e = 0; e < EDIM; e++)
                pl[mt][h][e] = 0.0f;

    #pragma unroll
    for (int nt = 0; nt < 8; nt++)
        #pragma unroll
        for (int i = 0; i < 2; i++) {
            const int cc = nw * 64 + nt * 8 + (ln & 3) * 2 + i;
            const float bb = b1s[cc];
            float w2e[EDIM];
            #pragma unroll
            for (int e = 0; e < EDIM; e++) w2e[e] = w2s[cc * EDIM + e];
            #pragma unroll
            for (int mt = 0; mt < 2; mt++)
                #pragma unroll
                for (int h = 0; h < 2; h++) {
                    float hv = fmaxf(c[mt][nt][h * 2 + i] + bb, 0.0f);
                    #pragma unroll
                    for (int e = 0; e < EDIM; e++)
                        pl[mt][h][e] = fmaf(hv, w2e[e], pl[mt][h][e]);
                }
        }

    #pragma unroll
    for (int off = 1; off < 4; off <<= 1)
        #pragma unroll
        for (int mt = 0; mt < 2; mt++)
            #pragma unroll
            for (int h = 0; h < 2; h++)
                #pragma unroll
                for (int e = 0; e < EDIM; e++)
                    pl[mt][h][e] += __shfl_xor_sync(0xffffffffu, pl[mt][h][e], off);

    if ((ln & 3) == 0) {
        #pragma unroll
        for (int mt = 0; mt < 2; mt++)
            #pragma unroll
            for (int h = 0; h < 2; h++) {
                const int r = mw * 32 + mt * 16 + (ln >> 2) + 8 * h;
                #pragma unroll
                for (int e = 0; e < EDIM; e++)
                    plog[(r * 4 + nw) * EDIM + e] = pl[mt][h][e];
            }
    }
    __syncthreads();

    // ---- top-2 + softmax + scatter + tie flag ----
    if (tid < BM) {
        const long long row = row0 + tid;
        float l[EDIM];
        #pragma unroll
        for (int e = 0; e < EDIM; e++) {
            float s = b2s[e];
            #pragma unroll
            for (int w = 0; w < 4; w++) s += plog[(tid * 4 + w) * EDIM + e];
            l[e] = s;
        }
        int i1 = 0;
        #pragma unroll
        for (int e = 1; e < EDIM; e++) if (l[e] > l[i1]) i1 = e;
        int i2 = (i1 == 0) ? 1 : 0;
        #pragma unroll
        for (int e = 0; e < EDIM; e++) if (e != i1 && l[e] > l[i2]) i2 = e;
        float m3 = -3.4e38f;
        #pragma unroll
        for (int e = 0; e < EDIM; e++) if (e != i1 && e != i2 && l[e] > m3) m3 = l[e];

        float e2  = __expf(l[i2] - l[i1]);
        float inv = 1.0f / (1.0f + e2);
        #pragma unroll
        for (int e = 0; e < EDIM; e++)
            out_gates[row * EDIM + e] = (e == i1) ? inv : ((e == i2) ? e2 * inv : 0.0f);
        if (write_idx) {
            out_idx[row * 2 + 0] = (float)i1;
            out_idx[row * 2 + 1] = (float)i2;
        }
        if ((l[i1] - l[i2] < TAU) || (l[i2] - m3 < TAU)) {
            int pos = atomicAdd(&g_count, 1);
            if (pos < FIXCAP) g_rows[pos] = (int)row;
        }
    }
}

// ===================== kernel 2: batched exact fp32 fixup =====================
__global__ __launch_bounds__(256)
void fixup_kernel(const float* __restrict__ x,
                  const float* __restrict__ W1,
                  const float* __restrict__ b1,
                  const float* __restrict__ W2,
                  const float* __restrict__ b2,
                  float* __restrict__ out_gates,
                  float* __restrict__ out_idx,
                  int write_idx)
{
    int cnt = g_count; if (cnt > FIXCAP) cnt = FIXCAP;
    const int base = blockIdx.x * RPF;
    if (base >= cnt) return;
    const int nr = min(RPF, cnt - base);
    const int tid = threadIdx.x;
    const int wrp = tid >> 5, ln = tid & 31;

    __shared__ float xs[RPF][DDIM];   // 16 KB
    __shared__ float hs[RPF][DDIM];   // 16 KB

    for (int r = 0; r < nr; r++)
        xs[r][tid] = x[(long long)g_rows[base + r] * DDIM + tid];
    __syncthreads();

    // h[r][tid] = relu(sum_k xs[r][k]*W1[k][tid] + b1[tid])
    float acc[RPF];
    #pragma unroll
    for (int r = 0; r < RPF; r++) acc[r] = 0.0f;
    for (int k = 0; k < DDIM; k++) {
        float w = W1[k * HDIM + tid];
        #pragma unroll
        for (int r = 0; r < RPF; r++)
            acc[r] = fmaf(xs[r][k], w, acc[r]);
    }
    const float bb1 = b1[tid];
    for (int r = 0; r < nr; r++)
        hs[r][tid] = fmaxf(acc[r] + bb1, 0.0f);
    __syncthreads();

    // each warp handles rows wrp, wrp+8
    for (int r = wrp; r < nr; r += 8) {
        float pl[EDIM] = {0.f, 0.f, 0.f, 0.f, 0.f};
        #pragma unroll
        for (int j = 0; j < 8; j++) {
            int n = ln * 8 + j;
            float hv = hs[r][n];
            #pragma unroll
            for (int e = 0; e < EDIM; e++)
                pl[e] = fmaf(hv, W2[n * EDIM + e], pl[e]);
        }
        #pragma unroll
        for (int off = 16; off > 0; off >>= 1)
            #pragma unroll
            for (int e = 0; e < EDIM; e++)
                pl[e] += __shfl_xor_sync(0xffffffffu, pl[e], off);

        if (ln == 0) {
            const long long row = g_rows[base + r];
            float l[EDIM];
            #pragma unroll
            for (int e = 0; e < EDIM; e++) l[e] = pl[e] + b2[e];
            int i1 = 0;
            #pragma unroll
            for (int e = 1; e < EDIM; e++) if (l[e] > l[i1]) i1 = e;
            int i2 = (i1 == 0) ? 1 : 0;
            #pragma unroll
            for (int e = 0; e < EDIM; e++) if (e != i1 && l[e] > l[i2]) i2 = e;
            float e2  = __expf(l[i2] - l[i1]);
            float inv = 1.0f / (1.0f + e2);
            #pragma unroll
            for (int e = 0; e < EDIM; e++)
                out_gates[row * EDIM + e] = (e == i1) ? inv : ((e == i2) ? e2 * inv : 0.0f);
            if (write_idx) {
                out_idx[row * 2 + 0] = (float)i1;
                out_idx[row * 2 + 1] = (float)i2;
            }
        }
    }
}

// ===================== launcher =====================
extern "C" void kernel_launch(void* const* d_in, const int* in_sizes, int n_in,
                              void* d_out, int out_size)
{
    const float* x  = (const float*)d_in[0];
    const float* W1 = (const float*)d_in[1];
    const float* b1 = (const float*)d_in[2];
    const float* W2 = (const float*)d_in[3];
    const float* b2 = (const float*)d_in[4];

    const long long Brows = (long long)in_sizes[0] / DDIM;
    float* gates = (float*)d_out;
    float* idxf  = gates + Brows * EDIM;
    int write_idx = ((long long)out_size >= Brows * (EDIM + 2)) ? 1 : 0;

    cudaFuncSetAttribute(gating_mma_kernel,
                         cudaFuncAttributeMaxDynamicSharedMemorySize, SMEM_TOTAL);

    prep_kernel<<<(DDIM * HDIM) / 256, 256>>>(W1);
    gating_mma_kernel<<<(unsigned)(Brows / BM), 256, SMEM_TOTAL>>>(
        x, b1, W2, b2, gates, idxf, write_idx);
    fixup_kernel<<<FIXCAP / RPF, 256>>>(x, W1, b1, W2, b2, gates, idxf, write_idx);
}

// round 5
// speedup vs baseline: 3.9901x; 1.0014x over previous
#include <cuda_runtime.h>
#include <cuda_fp16.h>
#include <cstdint>

// ===================== problem constants =====================
#define DDIM 256
#define HDIM 256
#define EDIM 5
#define BM   64            // rows per CTA
#define KC   32            // k per smem chunk (2 mma k-steps)
#define NCHUNK (DDIM / KC)
#define TAU  3e-3f
#define FIXCAP 16384
#define RPF  16            // rows per fixup block

// W smem leading dim (fp16 elements), padded for conflict-free ldmatrix
#define WS_LD 264          // 32 rows, stride 528B (16B-aligned)

// dynamic smem byte offsets
#define WS0_OFF   0        // 32*264*2 = 16896
#define WS1_OFF   16896
#define PLOG_OFF  33792    // float[64][4][5] = 5120
#define B1_OFF    38912    // float[256] = 1024
#define W2_OFF    39936    // float[256*5] = 5120
#define B2_OFF    45056    // float[8]
#define SMEM_TOTAL 45120

// ===================== device scratch =====================
__device__ int    g_count;
__device__ int    g_rows[FIXCAP];
__device__ __half g_w1h[DDIM * HDIM];   // W1 pre-converted to fp16, row-major [k][n]

// ===================== PTX helpers =====================
__device__ __forceinline__ uint32_t smem_u32(const void* p) {
    uint32_t a;
    asm("{ .reg .u64 t; cvta.to.shared.u64 t, %1; cvt.u32.u64 %0, t; }" : "=r"(a) : "l"(p));
    return a;
}

#define LDSM_X4_T(r0, r1, r2, r3, addr)                                            \
    asm volatile("ldmatrix.sync.aligned.m8n8.x4.trans.shared.b16 {%0,%1,%2,%3}, [%4];" \
        : "=r"(r0), "=r"(r1), "=r"(r2), "=r"(r3) : "r"(addr))

#define MMA_F16(d, a, b0, b1)                                                      \
    asm volatile("mma.sync.aligned.m16n8k16.row.col.f32.f16.f16.f32 "              \
        "{%0,%1,%2,%3}, {%4,%5,%6,%7}, {%8,%9}, {%0,%1,%2,%3};"                    \
        : "+f"((d)[0]), "+f"((d)[1]), "+f"((d)[2]), "+f"((d)[3])                   \
        : "r"((a)[0]), "r"((a)[1]), "r"((a)[2]), "r"((a)[3]), "r"(b0), "r"(b1))

#define CP_ASYNC16(dst, src)                                                       \
    asm volatile("cp.async.cg.shared.global [%0], [%1], 16;" :: "r"(dst), "l"(src))
#define CP_COMMIT() asm volatile("cp.async.commit_group;" ::: "memory")
#define CP_WAIT0()  asm volatile("cp.async.wait_group 0;" ::: "memory")

__device__ __forceinline__ uint32_t pack_h2(float a, float b) {
    __half2 v = __floats2half2_rn(a, b);
    return *reinterpret_cast<uint32_t*>(&v);
}

// ===================== kernel 0: prep (W1 -> fp16, zero counter) =====================
__global__ __launch_bounds__(256)
void prep_kernel(const float* __restrict__ W1) {
    int i = blockIdx.x * 256 + threadIdx.x;
    g_w1h[i] = __float2half(W1[i]);
    if (i == 0) g_count = 0;
}

// ===================== kernel 1: main fused mma kernel =====================
__global__ __launch_bounds__(256, 2)
void gating_mma_kernel(const float* __restrict__ x,
                       const float* __restrict__ b1,
                       const float* __restrict__ W2,
                       const float* __restrict__ b2,
                       float* __restrict__ out_gates,
                       float* __restrict__ out_idx,
                       int write_idx)
{
    extern __shared__ __align__(128) char smem[];
    const uint32_t sb = smem_u32(smem);
    const int tid  = threadIdx.x;
    const int wrp  = tid >> 5;
    const int ln   = tid & 31;
    const int mw   = wrp >> 2;           // 0..1 : warp row-block (32 rows)
    const int nw   = wrp & 3;            // 0..3 : warp col-block (64 cols)
    const long long row0 = (long long)blockIdx.x * BM;

    float* plog = (float*)(smem + PLOG_OFF);
    float* b1s  = (float*)(smem + B1_OFF);
    float* w2s  = (float*)(smem + W2_OFF);
    float* b2s  = (float*)(smem + B2_OFF);

    // aux tables
    b1s[tid] = b1[tid];
    if (tid < EDIM) b2s[tid] = b2[tid];
    #pragma unroll
    for (int i = 0; i < 5; i++) {
        int v = tid + i * 256;
        if (v < HDIM * EDIM) w2s[v] = W2[v];
    }

    // A row base offsets (4 rows per thread: mw*32 + (ln>>2) + {0,8,16,24})
    const float2* xg2 = (const float2*)x;
    size_t rb[4];
    #pragma unroll
    for (int i = 0; i < 4; i++)
        rb[i] = (size_t)(row0 + mw * 32 + (ln >> 2) + 8 * i) * DDIM;
    const int cth = (ln & 3) * 2;        // thread k-offset within 8-col group

    auto cp_async_W = [&](int chunk, uint32_t ws_off) {
        const __half* src_base = g_w1h + (size_t)(chunk * KC) * HDIM;
        #pragma unroll
        for (int t = 0; t < 4; t++) {
            int v   = tid + t * 256;     // 0..1023
            int r   = v >> 5;            // 0..31
            int g   = v & 31;            // 0..31
            uint32_t dst = sb + ws_off + (uint32_t)(r * (WS_LD * 2) + g * 16);
            CP_ASYNC16(dst, src_base + r * HDIM + g * 8);
        }
    };

    float c[2][8][4];
    #pragma unroll
    for (int mt = 0; mt < 2; mt++)
        #pragma unroll
        for (int nt = 0; nt < 8; nt++)
            #pragma unroll
            for (int r = 0; r < 4; r++)
                c[mt][nt][r] = 0.0f;

    // prologue: start W chunk 0
    cp_async_W(0, WS0_OFF);
    CP_COMMIT();

    #pragma unroll
    for (int kc = 0; kc < NCHUNK; kc++) {
        const int b = kc & 1;
        const uint32_t ws_off = b ? WS1_OFF : WS0_OFF;

        CP_WAIT0();                      // this thread's W copies for chunk kc done
        __syncthreads();                 // all threads' copies visible; prev buffer free
        if (kc + 1 < NCHUNK) {
            cp_async_W(kc + 1, b ? WS0_OFF : WS1_OFF);
            CP_COMMIT();
        }

        #pragma unroll
        for (int ks = 0; ks < 2; ks++) {
            const int k0 = kc * KC + ks * 16;
            // ---- A fragments straight from global (f32 -> f16 pack) ----
            uint32_t a[2][4];
            #pragma unroll
            for (int mt = 0; mt < 2; mt++) {
                const size_t r0o = rb[mt * 2 + 0];
                const size_t r1o = rb[mt * 2 + 1];
                float2 v00 = __ldg(&xg2[(r0o + k0 + cth) >> 1]);
                float2 v10 = __ldg(&xg2[(r1o + k0 + cth) >> 1]);
                float2 v01 = __ldg(&xg2[(r0o + k0 + cth + 8) >> 1]);
                float2 v11 = __ldg(&xg2[(r1o + k0 + cth + 8) >> 1]);
                a[mt][0] = pack_h2(v00.x, v00.y);
                a[mt][1] = pack_h2(v10.x, v10.y);
                a[mt][2] = pack_h2(v01.x, v01.y);
                a[mt][3] = pack_h2(v11.x, v11.y);
            }
            // ---- B fragments via ldmatrix ----
            uint32_t bfr[4][4];
            {
                int br = ks * 16 + (ln & 7) + ((ln >> 3) & 1) * 8;
                #pragma unroll
                for (int ng = 0; ng < 4; ng++) {
                    int bc = nw * 64 + ng * 16 + (ln >> 4) * 8;
                    uint32_t off = (uint32_t)((br * WS_LD + bc) * 2);
                    LDSM_X4_T(bfr[ng][0], bfr[ng][1], bfr[ng][2], bfr[ng][3], sb + ws_off + off);
                }
            }
            #pragma unroll
            for (int mt = 0; mt < 2; mt++)
                #pragma unroll
                for (int ng = 0; ng < 4; ng++)
                    #pragma unroll
                    for (int hf = 0; hf < 2; hf++)
                        MMA_F16(c[mt][ng * 2 + hf], a[mt], bfr[ng][hf * 2], bfr[ng][hf * 2 + 1]);
        }
    }

    // ---- fused epilogue: bias + relu + GEMM2 partials ----
    float pl[2][2][EDIM];
    #pragma unroll
    for (int mt = 0; mt < 2; mt++)
        #pragma unroll
        for (int h = 0; h < 2; h++)
            #pragma unroll
            for (int e = 0; e < EDIM; e++)
                pl[mt][h][e] = 0.0f;

    #pragma unroll
    for (int nt = 0; nt < 8; nt++)
        #pragma unroll
        for (int i = 0; i < 2; i++) {
            const int cc = nw * 64 + nt * 8 + (ln & 3) * 2 + i;
            const float bb = b1s[cc];
            float w2e[EDIM];
            #pragma unroll
            for (int e = 0; e < EDIM; e++) w2e[e] = w2s[cc * EDIM + e];
            #pragma unroll
            for (int mt = 0; mt < 2; mt++)
                #pragma unroll
                for (int h = 0; h < 2; h++) {
                    float hv = fmaxf(c[mt][nt][h * 2 + i] + bb, 0.0f);
                    #pragma unroll
                    for (int e = 0; e < EDIM; e++)
                        pl[mt][h][e] = fmaf(hv, w2e[e], pl[mt][h][e]);
                }
        }

    #pragma unroll
    for (int off = 1; off < 4; off <<= 1)
        #pragma unroll
        for (int mt = 0; mt < 2; mt++)
            #pragma unroll
            for (int h = 0; h < 2; h++)
                #pragma unroll
                for (int e = 0; e < EDIM; e++)
                    pl[mt][h][e] += __shfl_xor_sync(0xffffffffu, pl[mt][h][e], off);

    if ((ln & 3) == 0) {
        #pragma unroll
        for (int mt = 0; mt < 2; mt++)
            #pragma unroll
            for (int h = 0; h < 2; h++) {
                const int r = mw * 32 + mt * 16 + (ln >> 2) + 8 * h;
                #pragma unroll
                for (int e = 0; e < EDIM; e++)
                    plog[(r * 4 + nw) * EDIM + e] = pl[mt][h][e];
            }
    }
    __syncthreads();

    // ---- top-2 + softmax + scatter + tie flag ----
    if (tid < BM) {
        const long long row = row0 + tid;
        float l[EDIM];
        #pragma unroll
        for (int e = 0; e < EDIM; e++) {
            float s = b2s[e];
            #pragma unroll
            for (int w = 0; w < 4; w++) s += plog[(tid * 4 + w) * EDIM + e];
            l[e] = s;
        }
        int i1 = 0;
        #pragma unroll
        for (int e = 1; e < EDIM; e++) if (l[e] > l[i1]) i1 = e;
        int i2 = (i1 == 0) ? 1 : 0;
        #pragma unroll
        for (int e = 0; e < EDIM; e++) if (e != i1 && l[e] > l[i2]) i2 = e;
        float m3 = -3.4e38f;
        #pragma unroll
        for (int e = 0; e < EDIM; e++) if (e != i1 && e != i2 && l[e] > m3) m3 = l[e];

        float e2  = __expf(l[i2] - l[i1]);
        float inv = 1.0f / (1.0f + e2);
        #pragma unroll
        for (int e = 0; e < EDIM; e++)
            out_gates[row * EDIM + e] = (e == i1) ? inv : ((e == i2) ? e2 * inv : 0.0f);
        if (write_idx) {
            out_idx[row * 2 + 0] = (float)i1;
            out_idx[row * 2 + 1] = (float)i2;
        }
        if ((l[i1] - l[i2] < TAU) || (l[i2] - m3 < TAU)) {
            int pos = atomicAdd(&g_count, 1);
            if (pos < FIXCAP) g_rows[pos] = (int)row;
        }
    }
}

// ===================== kernel 2: batched exact fp32 fixup =====================
__global__ __launch_bounds__(256)
void fixup_kernel(const float* __restrict__ x,
                  const float* __restrict__ W1,
                  const float* __restrict__ b1,
                  const float* __restrict__ W2,
                  const float* __restrict__ b2,
                  float* __restrict__ out_gates,
                  float* __restrict__ out_idx,
                  int write_idx)
{
    int cnt = g_count; if (cnt > FIXCAP) cnt = FIXCAP;
    const int base = blockIdx.x * RPF;
    if (base >= cnt) return;
    const int nr = min(RPF, cnt - base);
    const int tid = threadIdx.x;
    const int wrp = tid >> 5, ln = tid & 31;

    __shared__ float xs[RPF][DDIM];
    __shared__ float hs[RPF][DDIM];

    for (int r = 0; r < nr; r++)
        xs[r][tid] = x[(long long)g_rows[base + r] * DDIM + tid];
    __syncthreads();

    float acc[RPF];
    #pragma unroll
    for (int r = 0; r < RPF; r++) acc[r] = 0.0f;
    for (int k = 0; k < DDIM; k++) {
        float w = W1[k * HDIM + tid];
        #pragma unroll
        for (int r = 0; r < RPF; r++)
            acc[r] = fmaf(xs[r][k], w, acc[r]);
    }
    const float bb1 = b1[tid];
    for (int r = 0; r < nr; r++)
        hs[r][tid] = fmaxf(acc[r] + bb1, 0.0f);
    __syncthreads();

    for (int r = wrp; r < nr; r += 8) {
        float pl[EDIM] = {0.f, 0.f, 0.f, 0.f, 0.f};
        #pragma unroll
        for (int j = 0; j < 8; j++) {
            int n = ln * 8 + j;
            float hv = hs[r][n];
            #pragma unroll
            for (int e = 0; e < EDIM; e++)
                pl[e] = fmaf(hv, W2[n * EDIM + e], pl[e]);
        }
        #pragma unroll
        for (int off = 16; off > 0; off >>= 1)
            #pragma unroll
            for (int e = 0; e < EDIM; e++)
                pl[e] += __shfl_xor_sync(0xffffffffu, pl[e], off);

        if (ln == 0) {
            const long long row = g_rows[base + r];
            float l[EDIM];
            #pragma unroll
            for (int e = 0; e < EDIM; e++) l[e] = pl[e] + b2[e];
            int i1 = 0;
            #pragma unroll
            for (int e = 1; e < EDIM; e++) if (l[e] > l[i1]) i1 = e;
            int i2 = (i1 == 0) ? 1 : 0;
            #pragma unroll
            for (int e = 0; e < EDIM; e++) if (e != i1 && l[e] > l[i2]) i2 = e;
            float e2  = __expf(l[i2] - l[i1]);
            float inv = 1.0f / (1.0f + e2);
            #pragma unroll
            for (int e = 0; e < EDIM; e++)
                out_gates[row * EDIM + e] = (e == i1) ? inv : ((e == i2) ? e2 * inv : 0.0f);
            if (write_idx) {
                out_idx[row * 2 + 0] = (float)i1;
                out_idx[row * 2 + 1] = (float)i2;
            }
        }
    }
}

// ===================== launcher =====================
extern "C" void kernel_launch(void* const* d_in, const int* in_sizes, int n_in,
                              void* d_out, int out_size)
{
    const float* x  = (const float*)d_in[0];
    const float* W1 = (const float*)d_in[1];
    const float* b1 = (const float*)d_in[2];
    const float* W2 = (const float*)d_in[3];
    const float* b2 = (const float*)d_in[4];

    const long long Brows = (long long)in_sizes[0] / DDIM;
    float* gates = (float*)d_out;
    float* idxf  = gates + Brows * EDIM;
    int write_idx = ((long long)out_size >= Brows * (EDIM + 2)) ? 1 : 0;

    cudaFuncSetAttribute(gating_mma_kernel,
                         cudaFuncAttributeMaxDynamicSharedMemorySize, SMEM_TOTAL);

    prep_kernel<<<(DDIM * HDIM) / 256, 256>>>(W1);
    gating_mma_kernel<<<(unsigned)(Brows / BM), 256, SMEM_TOTAL>>>(
        x, b1, W2, b2, gates, idxf, write_idx);
    fixup_kernel<<<FIXCAP / RPF, 256>>>(x, W1, b1, W2, b2, gates, idxf, write_idx);
}